// round 16
// baseline (speedup 1.0000x reference)
#include <cuda_runtime.h>
#include <cuda_fp16.h>
#include <cstdint>

// ---- problem constants ----
#define BDIM 4
#define TDIM 4096
#define NTOK (BDIM * TDIM)      // 16384
#define DDIM 2048
#define KDIM 2048               // H*2*E
#define TS 100000
#define VOCAB 50257
#define M0 20011
#define M1 30011
#define M2 40009

// ---- device scratch (allocation-free rule) ----
__device__ __half g_e[(size_t)NTOK * KDIM];
__device__ __half g_w[(size_t)DDIM * KDIM];
__device__ __half g_v[(size_t)NTOK * DDIM];     // v in fp16
__device__ float  g_shh[NTOK];                  // per-token sum h^2
__device__ float  g_svv[NTOK];                  // per-token sum v^2 (fp32 acc)
__device__ float  g_shv[NTOK];                  // per-token sum (h*wh)(v*wv)

// ============================================================================
// Baseline-PTX helpers (NO tcgen05 — harness compiles plain sm_103)
// ============================================================================
__device__ __forceinline__ uint32_t smem_to_u32(const void* p) {
    uint32_t a;
    asm("{ .reg .u64 t; cvta.to.shared.u64 t, %1; cvt.u32.u64 %0, t; }"
        : "=r"(a) : "l"(p));
    return a;
}
__device__ __forceinline__ void cp_async16(uint32_t smem_addr, const void* gptr) {
    asm volatile("cp.async.cg.shared.global [%0], [%1], 16;"
                 :: "r"(smem_addr), "l"(gptr) : "memory");
}
__device__ __forceinline__ void cp_commit() {
    asm volatile("cp.async.commit_group;" ::: "memory");
}
template <int N>
__device__ __forceinline__ void cp_wait_group() {
    asm volatile("cp.async.wait_group %0;" :: "n"(N) : "memory");
}
__device__ __forceinline__ void ldsm_x4(uint32_t* r, uint32_t addr) {
    asm volatile("ldmatrix.sync.aligned.m8n8.x4.shared.b16 {%0,%1,%2,%3}, [%4];"
                 : "=r"(r[0]), "=r"(r[1]), "=r"(r[2]), "=r"(r[3]) : "r"(addr));
}
__device__ __forceinline__ void mma_f16(float* d, const uint32_t* a,
                                        uint32_t b0, uint32_t b1) {
    asm volatile(
        "mma.sync.aligned.m16n8k16.row.col.f32.f16.f16.f32 "
        "{%0,%1,%2,%3}, {%4,%5,%6,%7}, {%8,%9}, {%0,%1,%2,%3};"
        : "+f"(d[0]), "+f"(d[1]), "+f"(d[2]), "+f"(d[3])
        : "r"(a[0]), "r"(a[1]), "r"(a[2]), "r"(a[3]), "r"(b0), "r"(b1));
}

// ============================================================================
// Kernel 1 (fused prep): blocks [0, NTOK)           = hash+gather token rows
//                        blocks [NTOK, NTOK+DDIM)   = convert one Wv row
//                        blocks [NTOK+DDIM, +48)    = zero gate accumulators
// ============================================================================
#define ZBLK 48
__global__ __launch_bounds__(256) void prep_kernel(
    const int* __restrict__ input_ids,
    const float* __restrict__ tables2,
    const float* __restrict__ tables3,
    const float* __restrict__ Wv)
{
    int blk = blockIdx.x;
    int tid = threadIdx.x;

    if (blk >= NTOK + DDIM) {
        // ---- zero the 3 x NTOK fp32 gate accumulators (49152 floats) ----
        int z = (blk - NTOK - DDIM) * 256 + tid;     // 0..12287 (float4 idx)
        float4 zero = make_float4(0.f, 0.f, 0.f, 0.f);
        // lay the three arrays back-to-back logically: 3*16384/4 = 12288
        if (z < NTOK / 4)
            *reinterpret_cast<float4*>(g_shh + z * 4) = zero;
        else if (z < NTOK / 2)
            *reinterpret_cast<float4*>(g_svv + (z - NTOK / 4) * 4) = zero;
        else
            *reinterpret_cast<float4*>(g_shv + (z - NTOK / 2) * 4) = zero;
        return;
    }
    if (blk >= NTOK) {
        // ---- Wv row conversion ----
        int row = blk - NTOK;
        size_t base = (size_t)row * KDIM + tid * 8;
        float4 x0 = *reinterpret_cast<const float4*>(Wv + base);
        float4 x1 = *reinterpret_cast<const float4*>(Wv + base + 4);
        float xs[8] = {x0.x, x0.y, x0.z, x0.w, x1.x, x1.y, x1.z, x1.w};
        __half h[8];
        #pragma unroll
        for (int j = 0; j < 8; j++) h[j] = __float2half_rn(xs[j]);
        *reinterpret_cast<uint4*>(g_w + base) = *reinterpret_cast<uint4*>(h);
        return;
    }

    // ---- gather path: one token per block ----
    int t = blk;
    __shared__ int s_i2, s_i3;
    if (tid == 0) {
        int b = t / TDIM;
        int tt = t % TDIM;
        const int* row = input_ids + (size_t)b * TDIM;
        int id0 = row[tt];
        id0 = id0 < 0 ? 0 : (id0 > VOCAB - 1 ? VOCAB - 1 : id0);
        int s1 = 0, s2 = 0;
        if (tt >= 1) { s1 = row[tt - 1]; s1 = s1 < 0 ? 0 : (s1 > VOCAB - 1 ? VOCAB - 1 : s1); }
        if (tt >= 2) { s2 = row[tt - 2]; s2 = s2 < 0 ? 0 : (s2 > VOCAB - 1 ? VOCAB - 1 : s2); }
        int hash2 = (id0 * M0) ^ (s1 * M1);
        int hash3 = hash2 ^ (s2 * M2);
        int i2 = hash2 % TS; if (i2 < 0) i2 = 0;
        int i3 = hash3 % TS; if (i3 < 0) i3 = 0;
        s_i2 = i2; s_i3 = i3;
    }
    __syncthreads();
    int i2 = s_i2, i3 = s_i3;

    int f0 = tid * 8;
    int seg = f0 >> 8;
    int off = f0 & 255;
    const float* src = (seg < 4)
        ? tables2 + ((size_t)seg * TS + i2) * 256 + off
        : tables3 + ((size_t)(seg - 4) * TS + i3) * 256 + off;
    float4 x0 = *reinterpret_cast<const float4*>(src);
    float4 x1 = *reinterpret_cast<const float4*>(src + 4);
    float xs[8] = {x0.x, x0.y, x0.z, x0.w, x1.x, x1.y, x1.z, x1.w};
    __half h[8];
    #pragma unroll
    for (int j = 0; j < 8; j++) h[j] = __float2half_rn(xs[j]);
    *reinterpret_cast<uint4*>(g_e + (size_t)t * KDIM + f0) =
        *reinterpret_cast<uint4*>(h);
}

// ============================================================================
// Kernel 2: fp16 GEMM via mma.sync (HMMA), fp32 accum in registers.
//   C[m][n] = sum_k e[m][k] * Wv[n][k]   both K-contiguous (NT)
//   CTA tile 128(M) x 64(N), 128 threads = 4 warps (2M x 2N), warp tile 64x32.
//   k-chunk 32, 4-stage cp.async pipeline (distance 3), launch_bounds(128,3).
//   Epilogue ALSO computes per-row gate partials (sum v^2, sum h^2,
//   sum (h*wh)(v*wv)) from the fp32 accumulators and atomicAdds them —
//   hidden is read under the tensor-bound mainloop's idle DRAM.
// ============================================================================
#define NK (KDIM / 32)            // 64 chunks
#define STAGES 4
#define STAGE_BYTES 12288
#define B_OFF 8192u
#define GEMM_SMEM (STAGES * STAGE_BYTES)   // 49152

__global__ __launch_bounds__(128, 3) void gemm_kernel(
    const float* __restrict__ hidden,
    const float* __restrict__ wh,
    const float* __restrict__ wv)
{
    extern __shared__ char smem[];
    const uint32_t sbase = smem_to_u32(smem);
    const int tid = threadIdx.x;
    const int lane = tid & 31;
    const int wid = tid >> 5;
    const int warpM = wid & 1;        // 2 warps in M
    const int warpN = wid >> 1;       // 2 warps in N
    const int m0 = blockIdx.y * 128;
    const int n0 = blockIdx.x * 64;

    // ---- per-thread cp.async mapping (6 x 16B per stage) ----
    const __half* src[6];
    uint32_t dstoff[6];
    #pragma unroll
    for (int i = 0; i < 6; i++) {
        int g = tid + i * 128;               // 0..767
        int isB = g >= 512;
        int gl = isB ? (g - 512) : g;        // A: 0..511, B: 0..255
        int row = gl >> 2;                   // A: 0..127, B: 0..63
        int ch = gl & 3;                     // 16B unit within 64B row
        const __half* base = isB ? g_w : g_e;
        int rowg = (isB ? n0 : m0) + row;
        src[i] = base + (size_t)rowg * KDIM + ch * 8;
        dstoff[i] = (isB ? B_OFF : 0u) + (uint32_t)row * 64u
                  + (uint32_t)((ch ^ ((row >> 1) & 3)) << 4);
    }

    // ---- ldmatrix address components (verified geometry) ----
    const int l15 = lane & 15;
    const int lhi = lane >> 4;
    const int s = (l15 >> 1) & 3;
    const uint32_t aRowBase = (uint32_t)(warpM * 64 + l15) * 64u;
    const uint32_t bRowBase = B_OFF + (uint32_t)(warpN * 32 + l15) * 64u;
    const uint32_t chj[2] = { (uint32_t)((lhi ^ s) << 4),
                              (uint32_t)(((2 + lhi) ^ s) << 4) };

    float acc[4][4][4];
    #pragma unroll
    for (int mf = 0; mf < 4; mf++)
        #pragma unroll
        for (int nf = 0; nf < 4; nf++)
            #pragma unroll
            for (int q = 0; q < 4; q++) acc[mf][nf][q] = 0.f;

    // ---- prologue: preload stages 0..2 ----
    #pragma unroll
    for (int st = 0; st < 3; st++) {
        uint32_t sb = sbase + st * STAGE_BYTES;
        #pragma unroll
        for (int i = 0; i < 6; i++)
            cp_async16(sb + dstoff[i], src[i] + st * 32);
        cp_commit();
    }

    for (int kt = 0; kt < NK; kt++) {
        if (kt <= NK - 3)      cp_wait_group<2>();
        else if (kt == NK - 2) cp_wait_group<1>();
        else                   cp_wait_group<0>();
        __syncthreads();

        if (kt + 3 < NK) {
            uint32_t sb = sbase + ((kt + 3) & 3) * STAGE_BYTES;
            #pragma unroll
            for (int i = 0; i < 6; i++)
                cp_async16(sb + dstoff[i], src[i] + (kt + 3) * 32);
            cp_commit();
        }

        const uint32_t sb = sbase + (kt & 3) * STAGE_BYTES;
        #pragma unroll
        for (int j = 0; j < 2; j++) {        // two k16 halves of the k32 chunk
            const uint32_t co = chj[j];
            uint32_t a[4][4];
            uint32_t b[2][4];
            #pragma unroll
            for (int mf = 0; mf < 4; mf++)
                ldsm_x4(a[mf], sb + aRowBase + (uint32_t)(mf * 1024) + co);
            #pragma unroll
            for (int nh = 0; nh < 2; nh++)
                ldsm_x4(b[nh], sb + bRowBase + (uint32_t)(nh * 1024) + co);

            #pragma unroll
            for (int mf = 0; mf < 4; mf++)
                #pragma unroll
                for (int nf = 0; nf < 4; nf++) {
                    const int nh = nf >> 1, su = nf & 1;
                    mma_f16(acc[mf][nf], a[mf], b[nh][su], b[nh][su + 2]);
                }
        }
    }

    // ---- epilogue: write fp16 v + per-row gate partials ----
    const int grp = lane >> 2;
    const int q2 = (lane & 3) * 2;

    // per-thread weight slice (8 cols, shared across all its rows)
    float whx[4][2], wvx[4][2];
    #pragma unroll
    for (int nf = 0; nf < 4; nf++) {
        int c = n0 + warpN * 32 + nf * 8 + q2;
        float2 a2 = *reinterpret_cast<const float2*>(wh + c);
        float2 b2 = *reinterpret_cast<const float2*>(wv + c);
        whx[nf][0] = a2.x; whx[nf][1] = a2.y;
        wvx[nf][0] = b2.x; wvx[nf][1] = b2.y;
    }

    #pragma unroll
    for (int mf = 0; mf < 4; mf++) {
        #pragma unroll
        for (int half = 0; half < 2; half++) {
            int r = m0 + warpM * 64 + mf * 16 + grp + half * 8;
            float svv = 0.f, shh = 0.f, shv = 0.f;
            #pragma unroll
            for (int nf = 0; nf < 4; nf++) {
                int c = n0 + warpN * 32 + nf * 8 + q2;
                float v0 = acc[mf][nf][half * 2];
                float v1 = acc[mf][nf][half * 2 + 1];
                float2 h2 = *reinterpret_cast<const float2*>(
                    hidden + (size_t)r * DDIM + c);
                svv += v0 * v0 + v1 * v1;
                shh += h2.x * h2.x + h2.y * h2.y;
                shv += (h2.x * whx[nf][0]) * (v0 * wvx[nf][0])
                     + (h2.y * whx[nf][1]) * (v1 * wvx[nf][1]);
                // write fp16 v
                __half2 vh = __floats2half2_rn(v0, v1);
                *reinterpret_cast<__half2*>(g_v + (size_t)r * DDIM + c) = vh;
            }
            // quad reduce (lanes grp*4..grp*4+3 share row r)
            svv += __shfl_xor_sync(0xffffffffu, svv, 1);
            svv += __shfl_xor_sync(0xffffffffu, svv, 2);
            shh += __shfl_xor_sync(0xffffffffu, shh, 1);
            shh += __shfl_xor_sync(0xffffffffu, shh, 2);
            shv += __shfl_xor_sync(0xffffffffu, shv, 1);
            shv += __shfl_xor_sync(0xffffffffu, shv, 2);
            if ((lane & 3) == 0) {
                atomicAdd(&g_svv[r], svv);
                atomicAdd(&g_shh[r], shh);
                atomicAdd(&g_shv[r], shv);
            }
        }
    }
}

// ============================================================================
// Kernel 3: gating (slim).  One block per token, 256 threads.
// Reads precomputed sums + v fp16, writes out fp32.  192 MB total.
// ============================================================================
__global__ __launch_bounds__(256) void gate_kernel(float* __restrict__ out)
{
    int t = blockIdx.x;
    int tid = threadIdx.x;
    int idx = tid * 8;

    float thh = __ldg(&g_shh[t]);
    float tvv = __ldg(&g_svv[t]);
    float thv = __ldg(&g_shv[t]);

    const float eps = 1.1920928955078125e-7f;
    float rh = rsqrtf(thh * (1.f / DDIM) + eps);
    float rv = rsqrtf(tvv * (1.f / DDIM) + eps);
    float gate = thv * rh * rv * (1.f / 45.254833995939045f);
    float ga = fabsf(gate);
    ga = fmaxf(ga, 1e-6f);
    float gs = copysignf(sqrtf(ga), gate);
    float sig = 1.f / (1.f + expf(-gs));

    const __half* v = g_v + (size_t)t * DDIM + idx;
    uint4 vp = *reinterpret_cast<const uint4*>(v);
    float vx[8];
    {
        const uint32_t* p = reinterpret_cast<const uint32_t*>(&vp);
        #pragma unroll
        for (int k = 0; k < 4; k++) {
            float2 f = __half22float2(*reinterpret_cast<const __half2*>(p + k));
            vx[k * 2] = f.x; vx[k * 2 + 1] = f.y;
        }
    }

    float* o = out + (size_t)t * DDIM + idx;
    float4 o0 = make_float4(vx[0] * sig, vx[1] * sig, vx[2] * sig, vx[3] * sig);
    float4 o1 = make_float4(vx[4] * sig, vx[5] * sig, vx[6] * sig, vx[7] * sig);
    *reinterpret_cast<float4*>(o)     = o0;
    *reinterpret_cast<float4*>(o + 4) = o1;
}

// ---------------------------------------------------------------------------
extern "C" void kernel_launch(void* const* d_in, const int* in_sizes, int n_in,
                              void* d_out, int out_size)
{
    const float* hidden  = (const float*)d_in[0];
    const float* tables2 = (const float*)d_in[1];
    const float* tables3 = (const float*)d_in[2];
    const float* Wv      = (const float*)d_in[3];
    const float* wh      = (const float*)d_in[4];
    const float* wv      = (const float*)d_in[5];
    const int*   ids     = (const int*)d_in[6];
    float* out = (float*)d_out;

    static bool attr_set = false;
    if (!attr_set) {
        cudaFuncSetAttribute(gemm_kernel,
                             cudaFuncAttributeMaxDynamicSharedMemorySize, GEMM_SMEM);
        attr_set = true;
    }

    prep_kernel<<<NTOK + DDIM + ZBLK, 256>>>(ids, tables2, tables3, Wv);

    dim3 grid(DDIM / 64, NTOK / 128);   // (32, 128); x-major shares A in L2
    gemm_kernel<<<grid, 128, GEMM_SMEM>>>(hidden, wh, wv);

    gate_kernel<<<NTOK, 256>>>(out);
}

// round 17
// speedup vs baseline: 1.5051x; 1.5051x over previous
#include <cuda_runtime.h>
#include <cuda_fp16.h>
#include <cstdint>

// ---- problem constants ----
#define BDIM 4
#define TDIM 4096
#define NTOK (BDIM * TDIM)      // 16384
#define DDIM 2048
#define KDIM 2048               // H*2*E
#define TS 100000
#define VOCAB 50257
#define M0 20011
#define M1 30011
#define M2 40009

// ---- device scratch (allocation-free rule) ----
__device__ __half g_e[(size_t)NTOK * KDIM];
__device__ __half g_w[(size_t)DDIM * KDIM];
__device__ __half g_v[(size_t)NTOK * DDIM];     // v in fp16

// ============================================================================
// Baseline-PTX helpers (NO tcgen05 — harness compiles plain sm_103)
// ============================================================================
__device__ __forceinline__ uint32_t smem_to_u32(const void* p) {
    uint32_t a;
    asm("{ .reg .u64 t; cvta.to.shared.u64 t, %1; cvt.u32.u64 %0, t; }"
        : "=r"(a) : "l"(p));
    return a;
}
__device__ __forceinline__ void cp_async16(uint32_t smem_addr, const void* gptr) {
    asm volatile("cp.async.cg.shared.global [%0], [%1], 16;"
                 :: "r"(smem_addr), "l"(gptr) : "memory");
}
__device__ __forceinline__ void cp_commit() {
    asm volatile("cp.async.commit_group;" ::: "memory");
}
template <int N>
__device__ __forceinline__ void cp_wait_group() {
    asm volatile("cp.async.wait_group %0;" :: "n"(N) : "memory");
}
__device__ __forceinline__ void ldsm_x4(uint32_t* r, uint32_t addr) {
    asm volatile("ldmatrix.sync.aligned.m8n8.x4.shared.b16 {%0,%1,%2,%3}, [%4];"
                 : "=r"(r[0]), "=r"(r[1]), "=r"(r[2]), "=r"(r[3]) : "r"(addr));
}
__device__ __forceinline__ void mma_f16(float* d, const uint32_t* a,
                                        uint32_t b0, uint32_t b1) {
    asm volatile(
        "mma.sync.aligned.m16n8k16.row.col.f32.f16.f16.f32 "
        "{%0,%1,%2,%3}, {%4,%5,%6,%7}, {%8,%9}, {%0,%1,%2,%3};"
        : "+f"(d[0]), "+f"(d[1]), "+f"(d[2]), "+f"(d[3])
        : "r"(a[0]), "r"(a[1]), "r"(a[2]), "r"(a[3]), "r"(b0), "r"(b1));
}

// ============================================================================
// Kernel 1 (fused prep): blocks [0, NTOK) = hash+gather token rows;
//                        blocks [NTOK, NTOK+DDIM) = convert one Wv row.
// ============================================================================
__global__ __launch_bounds__(256) void prep_kernel(
    const int* __restrict__ input_ids,
    const float* __restrict__ tables2,
    const float* __restrict__ tables3,
    const float* __restrict__ Wv)
{
    int blk = blockIdx.x;
    int tid = threadIdx.x;

    if (blk >= NTOK) {
        // ---- Wv row conversion: one row of 2048 floats per block ----
        int row = blk - NTOK;
        size_t base = (size_t)row * KDIM + tid * 8;
        float4 x0 = *reinterpret_cast<const float4*>(Wv + base);
        float4 x1 = *reinterpret_cast<const float4*>(Wv + base + 4);
        float xs[8] = {x0.x, x0.y, x0.z, x0.w, x1.x, x1.y, x1.z, x1.w};
        __half h[8];
        #pragma unroll
        for (int j = 0; j < 8; j++) h[j] = __float2half_rn(xs[j]);
        *reinterpret_cast<uint4*>(g_w + base) = *reinterpret_cast<uint4*>(h);
        return;
    }

    // ---- gather path: one token per block ----
    int t = blk;
    __shared__ int s_i2, s_i3;
    if (tid == 0) {
        int b = t / TDIM;
        int tt = t % TDIM;
        const int* row = input_ids + (size_t)b * TDIM;
        int id0 = row[tt];
        id0 = id0 < 0 ? 0 : (id0 > VOCAB - 1 ? VOCAB - 1 : id0);
        int s1 = 0, s2 = 0;
        if (tt >= 1) { s1 = row[tt - 1]; s1 = s1 < 0 ? 0 : (s1 > VOCAB - 1 ? VOCAB - 1 : s1); }
        if (tt >= 2) { s2 = row[tt - 2]; s2 = s2 < 0 ? 0 : (s2 > VOCAB - 1 ? VOCAB - 1 : s2); }
        int hash2 = (id0 * M0) ^ (s1 * M1);
        int hash3 = hash2 ^ (s2 * M2);
        int i2 = hash2 % TS; if (i2 < 0) i2 = 0;
        int i3 = hash3 % TS; if (i3 < 0) i3 = 0;
        s_i2 = i2; s_i3 = i3;
    }
    __syncthreads();
    int i2 = s_i2, i3 = s_i3;

    int f0 = tid * 8;
    int seg = f0 >> 8;
    int off = f0 & 255;
    const float* src = (seg < 4)
        ? tables2 + ((size_t)seg * TS + i2) * 256 + off
        : tables3 + ((size_t)(seg - 4) * TS + i3) * 256 + off;
    float4 x0 = *reinterpret_cast<const float4*>(src);
    float4 x1 = *reinterpret_cast<const float4*>(src + 4);
    float xs[8] = {x0.x, x0.y, x0.z, x0.w, x1.x, x1.y, x1.z, x1.w};
    __half h[8];
    #pragma unroll
    for (int j = 0; j < 8; j++) h[j] = __float2half_rn(xs[j]);
    *reinterpret_cast<uint4*>(g_e + (size_t)t * KDIM + f0) =
        *reinterpret_cast<uint4*>(h);
}

// ============================================================================
// Kernel 2: fp16 GEMM via mma.sync (HMMA), fp32 accum in registers.
//   C[m][n] = sum_k e[m][k] * Wv[n][k]   both K-contiguous (NT)
//   CTA tile 128(M) x 128(N), 128 threads = 4 warps (2M x 2N),
//   warp tile 64x64 -> 2x MMA per LDSM (smem-crossbar relief).
//   k-chunk 32, 4-stage cp.async pipeline (distance 3).
//   __launch_bounds__(128, 2): 256-reg budget (natural ~190, no spills),
//   2 CTAs/SM -> each SMSP holds warps from INDEPENDENT CTAs.
// Stage (16KB): A @0: 128 rows x 64B; B @8192: 128 rows x 64B.
//   16B-unit swizzle: c ^= (row>>1)&3.
// ============================================================================
#define NK (KDIM / 32)            // 64 chunks
#define STAGES 4
#define STAGE_BYTES 16384
#define B_OFF 8192u
#define GEMM_SMEM (STAGES * STAGE_BYTES)   // 65536

__global__ __launch_bounds__(128, 2) void gemm_kernel()
{
    extern __shared__ char smem[];
    const uint32_t sbase = smem_to_u32(smem);
    const int tid = threadIdx.x;
    const int lane = tid & 31;
    const int wid = tid >> 5;
    const int warpM = wid & 1;        // 2 warps in M
    const int warpN = wid >> 1;       // 2 warps in N
    const int m0 = blockIdx.y * 128;
    const int n0 = blockIdx.x * 128;

    // ---- per-thread cp.async mapping (8 x 16B per stage) ----
    const __half* src[8];
    uint32_t dstoff[8];
    #pragma unroll
    for (int i = 0; i < 8; i++) {
        int g = tid + i * 128;               // 0..1023
        int isB = g >= 512;
        int gl = g & 511;
        int row = gl >> 2;                   // 0..127
        int ch = gl & 3;                     // 16B unit within 64B row
        const __half* base = isB ? g_w : g_e;
        int rowg = (isB ? n0 : m0) + row;
        src[i] = base + (size_t)rowg * KDIM + ch * 8;
        dstoff[i] = (isB ? B_OFF : 0u) + (uint32_t)row * 64u
                  + (uint32_t)((ch ^ ((row >> 1) & 3)) << 4);
    }

    // ---- ldmatrix address components (verified geometry) ----
    const int l15 = lane & 15;
    const int lhi = lane >> 4;
    const int s = (l15 >> 1) & 3;
    const uint32_t aRowBase = (uint32_t)(warpM * 64 + l15) * 64u;
    const uint32_t bRowBase = B_OFF + (uint32_t)(warpN * 64 + l15) * 64u;
    const uint32_t chj[2] = { (uint32_t)((lhi ^ s) << 4),
                              (uint32_t)(((2 + lhi) ^ s) << 4) };

    float acc[4][8][4];
    #pragma unroll
    for (int mf = 0; mf < 4; mf++)
        #pragma unroll
        for (int nf = 0; nf < 8; nf++)
            #pragma unroll
            for (int q = 0; q < 4; q++) acc[mf][nf][q] = 0.f;

    // ---- prologue: preload stages 0..2 ----
    #pragma unroll
    for (int st = 0; st < 3; st++) {
        uint32_t sb = sbase + st * STAGE_BYTES;
        #pragma unroll
        for (int i = 0; i < 8; i++)
            cp_async16(sb + dstoff[i], src[i] + st * 32);
        cp_commit();
    }

    for (int kt = 0; kt < NK; kt++) {
        if (kt <= NK - 3)      cp_wait_group<2>();
        else if (kt == NK - 2) cp_wait_group<1>();
        else                   cp_wait_group<0>();
        __syncthreads();

        if (kt + 3 < NK) {
            uint32_t sb = sbase + ((kt + 3) & 3) * STAGE_BYTES;
            #pragma unroll
            for (int i = 0; i < 8; i++)
                cp_async16(sb + dstoff[i], src[i] + (kt + 3) * 32);
            cp_commit();
        }

        const uint32_t sb = sbase + (kt & 3) * STAGE_BYTES;
        #pragma unroll
        for (int j = 0; j < 2; j++) {        // two k16 halves of the k32 chunk
            const uint32_t co = chj[j];
            uint32_t a[4][4];
            uint32_t b[4][4];
            #pragma unroll
            for (int mf = 0; mf < 4; mf++)
                ldsm_x4(a[mf], sb + aRowBase + (uint32_t)(mf * 1024) + co);
            #pragma unroll
            for (int nh = 0; nh < 4; nh++)
                ldsm_x4(b[nh], sb + bRowBase + (uint32_t)(nh * 1024) + co);

            #pragma unroll
            for (int mf = 0; mf < 4; mf++)
                #pragma unroll
                for (int nf = 0; nf < 8; nf++) {
                    const int nh = nf >> 1, su = nf & 1;
                    mma_f16(acc[mf][nf], a[mf], b[nh][su], b[nh][su + 2]);
                }
        }
    }

    // ---- epilogue: write fp16 result ----
    const int grp = lane >> 2;
    const int q2 = (lane & 3) * 2;
    #pragma unroll
    for (int mf = 0; mf < 4; mf++) {
        #pragma unroll
        for (int nf = 0; nf < 8; nf++) {
            int r = m0 + warpM * 64 + mf * 16 + grp;
            int c = n0 + warpN * 64 + nf * 8 + q2;
            __half2 v0 = __floats2half2_rn(acc[mf][nf][0], acc[mf][nf][1]);
            __half2 v1 = __floats2half2_rn(acc[mf][nf][2], acc[mf][nf][3]);
            *reinterpret_cast<__half2*>(g_v + (size_t)r * DDIM + c) = v0;
            *reinterpret_cast<__half2*>(g_v + (size_t)(r + 8) * DDIM + c) = v1;
        }
    }
}

// ============================================================================
// Kernel 3: gating.  One block per token, 256 threads, 8 elems/thread.
// v is fp16; everything else fp32.  (round-14 verified version)
// ============================================================================
__global__ __launch_bounds__(256) void gate_kernel(
    const float* __restrict__ hidden,
    const float* __restrict__ wh,
    const float* __restrict__ wv,
    float* __restrict__ out)
{
    int t = blockIdx.x;
    int tid = threadIdx.x;
    int idx = tid * 8;
    const float* h = hidden + (size_t)t * DDIM + idx;
    const __half* v = g_v + (size_t)t * DDIM + idx;

    float4 h0 = *reinterpret_cast<const float4*>(h);
    float4 h1 = *reinterpret_cast<const float4*>(h + 4);
    uint4 vp = *reinterpret_cast<const uint4*>(v);
    float4 w0 = *reinterpret_cast<const float4*>(wh + idx);
    float4 w1 = *reinterpret_cast<const float4*>(wh + idx + 4);
    float4 u0 = *reinterpret_cast<const float4*>(wv + idx);
    float4 u1 = *reinterpret_cast<const float4*>(wv + idx + 4);

    float hx[8] = {h0.x, h0.y, h0.z, h0.w, h1.x, h1.y, h1.z, h1.w};
    float whx[8] = {w0.x, w0.y, w0.z, w0.w, w1.x, w1.y, w1.z, w1.w};
    float wvx[8] = {u0.x, u0.y, u0.z, u0.w, u1.x, u1.y, u1.z, u1.w};
    float vx[8];
    {
        const uint32_t* p = reinterpret_cast<const uint32_t*>(&vp);
        #pragma unroll
        for (int k = 0; k < 4; k++) {
            float2 f = __half22float2(*reinterpret_cast<const __half2*>(p + k));
            vx[k * 2] = f.x; vx[k * 2 + 1] = f.y;
        }
    }

    float shh = 0.f, svv = 0.f, shv = 0.f;
    #pragma unroll
    for (int j = 0; j < 8; j++) {
        shh += hx[j] * hx[j];
        svv += vx[j] * vx[j];
        shv += (hx[j] * whx[j]) * (vx[j] * wvx[j]);
    }

    #pragma unroll
    for (int o = 16; o > 0; o >>= 1) {
        shh += __shfl_down_sync(0xffffffffu, shh, o);
        svv += __shfl_down_sync(0xffffffffu, svv, o);
        shv += __shfl_down_sync(0xffffffffu, shv, o);
    }
    __shared__ float s0[8], s1[8], s2[8];
    int warp = tid >> 5, lane = tid & 31;
    if (lane == 0) { s0[warp] = shh; s1[warp] = svv; s2[warp] = shv; }
    __syncthreads();
    float thh = 0.f, tvv = 0.f, thv = 0.f;
    #pragma unroll
    for (int w = 0; w < 8; w++) { thh += s0[w]; tvv += s1[w]; thv += s2[w]; }

    const float eps = 1.1920928955078125e-7f;
    float rh = rsqrtf(thh * (1.f / DDIM) + eps);
    float rv = rsqrtf(tvv * (1.f / DDIM) + eps);
    float gate = thv * rh * rv * (1.f / 45.254833995939045f);
    float ga = fabsf(gate);
    ga = fmaxf(ga, 1e-6f);
    float gs = copysignf(sqrtf(ga), gate);
    float sig = 1.f / (1.f + expf(-gs));

    float* o = out + (size_t)t * DDIM + idx;
    float4 o0 = make_float4(vx[0] * sig, vx[1] * sig, vx[2] * sig, vx[3] * sig);
    float4 o1 = make_float4(vx[4] * sig, vx[5] * sig, vx[6] * sig, vx[7] * sig);
    *reinterpret_cast<float4*>(o)     = o0;
    *reinterpret_cast<float4*>(o + 4) = o1;
}

// ---------------------------------------------------------------------------
extern "C" void kernel_launch(void* const* d_in, const int* in_sizes, int n_in,
                              void* d_out, int out_size)
{
    const float* hidden  = (const float*)d_in[0];
    const float* tables2 = (const float*)d_in[1];
    const float* tables3 = (const float*)d_in[2];
    const float* Wv      = (const float*)d_in[3];
    const float* wh      = (const float*)d_in[4];
    const float* wv      = (const float*)d_in[5];
    const int*   ids     = (const int*)d_in[6];
    float* out = (float*)d_out;

    static bool attr_set = false;
    if (!attr_set) {
        cudaFuncSetAttribute(gemm_kernel,
                             cudaFuncAttributeMaxDynamicSharedMemorySize, GEMM_SMEM);
        attr_set = true;
    }

    prep_kernel<<<NTOK + DDIM, 256>>>(ids, tables2, tables3, Wv);

    dim3 grid(DDIM / 128, NTOK / 128);   // (16, 128); x-major shares A in L2
    gemm_kernel<<<grid, 128, GEMM_SMEM>>>();

    gate_kernel<<<NTOK, 256>>>(hidden, wh, wv, out);
}